// round 16
// baseline (speedup 1.0000x reference)
#include <cuda_runtime.h>
#include <cuda_bf16.h>
#include <math.h>

// ---------------- problem constants ----------------
#define SEQ     2048
#define DMODEL  1024
#define HKN     8
#define DK      64
#define HV      16
#define DV      64
#define KEYD    512
#define VALD    1024
#define CONVD   2048
#define QZD     3072
#define KW      4
#define NE      8
#define TOPK    2
#define IMOE    512

#define OUT_X_OFF     0
#define OUT_STATE_OFF (SEQ*DMODEL)
#define OUT_CONV_OFF  (OUT_STATE_OFF + HV*DK*DV)

// ---------------- scratch ----------------
__device__ float g_h    [SEQ*DMODEL];
__device__ __nv_bfloat16 g_hh[SEQ*DMODEL], g_hl[SEQ*DMODEL];
__device__ float g_qkvz [SEQ*QZD];
__device__ float g_qkv  [SEQ*CONVD];
__device__ float g_qn   [SEQ*VALD];
__device__ float g_kn   [SEQ*VALD];
__device__ float g_beta [SEQ*HV];
__device__ float g_decay[SEQ*HV];
__device__ float g_o    [SEQ*VALD];
__device__ __nv_bfloat16 g_oh[SEQ*VALD], g_ol[SEQ*VALD];
__device__ float g_attn [SEQ*DMODEL];
__device__ float g_x2   [SEQ*DMODEL];
__device__ float g_t    [SEQ*DMODEL];
__device__ __nv_bfloat16 g_th[SEQ*DMODEL], g_tl[SEQ*DMODEL];
__device__ int   g_topi [SEQ*TOPK];
__device__ float g_topw [SEQ*TOPK];
__device__ int   g_pos  [SEQ*TOPK];
__device__ int   g_cnt  [NE];
__device__ int   g_list [NE*SEQ];
__device__ float g_gu   [(long)NE*SEQ*1024];
__device__ __nv_bfloat16 g_acth[(long)NE*SEQ*IMOE], g_actl[(long)NE*SEQ*IMOE];
__device__ float g_eo   [(long)NE*SEQ*DMODEL];
__device__ float g_sgu  [SEQ*2048];
__device__ __nv_bfloat16 g_sgh[SEQ*VALD], g_sgl[SEQ*VALD];
__device__ float g_sh   [SEQ*DMODEL];
__device__ float g_gate [SEQ];
__device__ __nv_bfloat16 g_wqzT_h [QZD*DMODEL],  g_wqzT_l [QZD*DMODEL];
__device__ __nv_bfloat16 g_woutT_h[DMODEL*VALD], g_woutT_l[DMODEL*VALD];
__device__ __nv_bfloat16 g_wguT_h [2048*DMODEL], g_wguT_l [2048*DMODEL];
__device__ __nv_bfloat16 g_wsdT_h [DMODEL*VALD], g_wsdT_l [DMODEL*VALD];
__device__ __nv_bfloat16 g_egu_h  [(long)NE*1024*DMODEL], g_egu_l[(long)NE*1024*DMODEL];
__device__ __nv_bfloat16 g_ed_h   [(long)NE*DMODEL*IMOE], g_ed_l [(long)NE*DMODEL*IMOE];

// ---------------- helpers ----------------
__device__ __forceinline__ float warp_reduce(float v) {
    #pragma unroll
    for (int o = 16; o > 0; o >>= 1) v += __shfl_xor_sync(0xffffffffu, v, o);
    return v;
}
__device__ __forceinline__ float siluf(float x) { return x / (1.f + expf(-x)); }
__device__ __forceinline__ float sigmoidf(float x) { return 1.f / (1.f + expf(-x)); }

__device__ __forceinline__ void mma_bf16(float* c, const unsigned* a, const unsigned* b) {
    asm volatile(
        "mma.sync.aligned.m16n8k16.row.col.f32.bf16.bf16.f32 "
        "{%0,%1,%2,%3}, {%4,%5,%6,%7}, {%8,%9}, {%0,%1,%2,%3};\n"
        : "+f"(c[0]), "+f"(c[1]), "+f"(c[2]), "+f"(c[3])
        : "r"(a[0]), "r"(a[1]), "r"(a[2]), "r"(a[3]), "r"(b[0]), "r"(b[1]));
}
__device__ __forceinline__ void ldsm4(unsigned* r, unsigned addr) {
    asm volatile("ldmatrix.sync.aligned.m8n8.x4.shared.b16 {%0,%1,%2,%3}, [%4];\n"
                 : "=r"(r[0]), "=r"(r[1]), "=r"(r[2]), "=r"(r[3]) : "r"(addr));
}
__device__ __forceinline__ void split_bf16(float v, __nv_bfloat16& hi, __nv_bfloat16& lo) {
    hi = __float2bfloat16(v);
    lo = __float2bfloat16(v - __bfloat162float(hi));
}
__device__ __forceinline__ void cp16(void* sptr, const void* gptr, bool valid) {
    unsigned s = (unsigned)__cvta_generic_to_shared(sptr);
    int sz = valid ? 16 : 0;
    asm volatile("cp.async.cg.shared.global [%0], [%1], 16, %2;\n"
                 :: "r"(s), "l"(gptr), "r"(sz));
}

// ---------------- weight prep ----------------
__global__ void tsplit_kernel(const float* __restrict__ W,
                              __nv_bfloat16* __restrict__ oh, __nv_bfloat16* __restrict__ ol,
                              int K, int N) {
    __shared__ float tile[32][33];
    int n0 = blockIdx.x * 32, k0 = blockIdx.y * 32;
    int tx = threadIdx.x & 31, ty = threadIdx.x >> 5;
    #pragma unroll
    for (int i = 0; i < 32; i += 8)
        tile[ty + i][tx] = W[(long)(k0 + ty + i) * N + n0 + tx];
    __syncthreads();
    #pragma unroll
    for (int i = 0; i < 32; i += 8) {
        float v = tile[tx][ty + i];
        __nv_bfloat16 h, l; split_bf16(v, h, l);
        long o = (long)(n0 + ty + i) * K + k0 + tx;
        oh[o] = h; ol[o] = l;
    }
}

__global__ void split_kernel(const float* __restrict__ in,
                             __nv_bfloat16* __restrict__ oh, __nv_bfloat16* __restrict__ ol,
                             long n4) {
    long i = (long)blockIdx.x * blockDim.x + threadIdx.x;
    if (i >= n4) return;
    float4 v = reinterpret_cast<const float4*>(in)[i];
    __nv_bfloat162 h01, l01, h23, l23;
    __nv_bfloat16 h, l;
    split_bf16(v.x, h, l); h01.x = h; l01.x = l;
    split_bf16(v.y, h, l); h01.y = h; l01.y = l;
    split_bf16(v.z, h, l); h23.x = h; l23.x = l;
    split_bf16(v.w, h, l); h23.y = h; l23.y = l;
    reinterpret_cast<__nv_bfloat162*>(oh)[2*i]   = h01;
    reinterpret_cast<__nv_bfloat162*>(oh)[2*i+1] = h23;
    reinterpret_cast<__nv_bfloat162*>(ol)[2*i]   = l01;
    reinterpret_cast<__nv_bfloat162*>(ol)[2*i+1] = l23;
}

// ---------------- rms norms ----------------
__global__ void rmsnorm_kernel(const float* __restrict__ x, const float* __restrict__ w,
                               float* __restrict__ y,
                               __nv_bfloat16* __restrict__ yh, __nv_bfloat16* __restrict__ yl) {
    int row = blockIdx.x, tid = threadIdx.x;
    const float* xr = x + (long)row * DMODEL;
    float v[4]; float ss = 0.f;
    #pragma unroll
    for (int i = 0; i < 4; i++) { v[i] = xr[tid + 256*i]; ss += v[i]*v[i]; }
    ss = warp_reduce(ss);
    __shared__ float sm[8]; __shared__ float rtot;
    if ((tid & 31) == 0) sm[tid >> 5] = ss;
    __syncthreads();
    if (tid == 0) {
        float t2 = 0.f;
        #pragma unroll
        for (int i = 0; i < 8; i++) t2 += sm[i];
        rtot = rsqrtf(t2 / (float)DMODEL + 1e-6f);
    }
    __syncthreads();
    float r = rtot;
    #pragma unroll
    for (int i = 0; i < 4; i++) {
        long o = (long)row * DMODEL + tid + 256*i;
        float val = v[i] * r * (1.f + w[tid + 256*i]);
        y[o] = val;
        __nv_bfloat16 h, l; split_bf16(val, h, l);
        yh[o] = h; yl[o] = l;
    }
}

__global__ void rmsnorm_add_kernel(const float* __restrict__ x, const float* __restrict__ add,
                                   const float* __restrict__ w,
                                   float* __restrict__ xsum, float* __restrict__ y,
                                   __nv_bfloat16* __restrict__ yh, __nv_bfloat16* __restrict__ yl) {
    int row = blockIdx.x, tid = threadIdx.x;
    const float* xr = x + (long)row * DMODEL;
    const float* ar = add + (long)row * DMODEL;
    float v[4]; float ss = 0.f;
    #pragma unroll
    for (int i = 0; i < 4; i++) { v[i] = xr[tid + 256*i] + ar[tid + 256*i]; ss += v[i]*v[i]; }
    ss = warp_reduce(ss);
    __shared__ float sm[8]; __shared__ float rtot;
    if ((tid & 31) == 0) sm[tid >> 5] = ss;
    __syncthreads();
    if (tid == 0) {
        float t2 = 0.f;
        #pragma unroll
        for (int i = 0; i < 8; i++) t2 += sm[i];
        rtot = rsqrtf(t2 / (float)DMODEL + 1e-6f);
    }
    __syncthreads();
    float r = rtot;
    #pragma unroll
    for (int i = 0; i < 4; i++) {
        long o = (long)row * DMODEL + tid + 256*i;
        xsum[o] = v[i];
        float val = v[i] * r * (1.f + w[tid + 256*i]);
        y[o] = val;
        __nv_bfloat16 h, l; split_bf16(val, h, l);
        yh[o] = h; yl[o] = l;
    }
}

// ---------------- bf16 GEMM 128x128x32, 3-stage cp.async, 1 bar/iter -------
#define SA 40
#define STAGE_A (128*SA)
#define STAGE_B (128*SA)
#define STAGE_TOT (2*STAGE_A + 2*STAGE_B)
#define NSTG 3
#define GEMM_SMEM (NSTG*STAGE_TOT*2)

template<bool AGATHER>
__global__ void __launch_bounds__(256, 1) gemm_bf16_kernel(
        const __nv_bfloat16* __restrict__ Ah_g, const __nv_bfloat16* __restrict__ Al_g,
        const __nv_bfloat16* __restrict__ Bh_g, const __nv_bfloat16* __restrict__ Bl_g,
        float* __restrict__ Cbase,
        int M, int N, int K,
        long aStride, long bStride, long cStride,
        const int* __restrict__ gIdx, const int* __restrict__ gCnt, int gCap) {
    extern __shared__ __nv_bfloat16 dsm[];

    const int e = blockIdx.z;
    const __nv_bfloat16* Agh = Ah_g + (long)e * aStride;
    const __nv_bfloat16* Agl = Al_g + (long)e * aStride;
    const __nv_bfloat16* Bgh = Bh_g + (long)e * bStride;
    const __nv_bfloat16* Bgl = Bl_g + (long)e * bStride;
    float* C = Cbase + (long)e * cStride;

    int Meff = M;
    const int* lst = nullptr;
    if (AGATHER) {
        Meff = gCnt[e];
        lst = gIdx ? (gIdx + e * gCap) : nullptr;
    }
    int m0 = blockIdx.y * 128, n0 = blockIdx.x * 128;
    if (m0 >= Meff) return;

    int tid = threadIdx.x;
    int wid = tid >> 5, lane = tid & 31;
    int mbase = (wid >> 2) * 64;
    int nbase = (wid & 3) * 32;
    int lr = lane & 7, grp = lane >> 3;

    unsigned aoff = ((mbase + (grp & 1)*8 + lr) * SA + (grp >> 1)*8) * 2;
    unsigned boff = ((nbase + (grp >> 1)*8 + lr) * SA + (grp & 1)*8) * 2;
    unsigned smBase = (unsigned)__cvta_generic_to_shared(dsm);

    const __nv_bfloat16* agp[4]; int adst[4]; bool alo[4], aval[4];
    #pragma unroll
    for (int i = 0; i < 4; i++) {
        int id = tid + 256*i;
        int r = id >> 3, ch = (id >> 1) & 3;
        bool lo = id & 1;
        int m = m0 + r;
        bool vld = m < Meff;
        long grow = 0;
        if (vld) grow = (AGATHER && lst) ? (long)lst[m] : (long)m;
        agp[i] = (lo ? Agl : Agh) + grow * K + ch * 8;
        adst[i] = r * SA + ch * 8;
        alo[i] = lo; aval[i] = vld;
    }
    const __nv_bfloat16* bgp[4]; int bdst[4]; bool blo[4];
    #pragma unroll
    for (int i = 0; i < 4; i++) {
        int id = tid + 256*i;
        int r = id >> 3, ch = (id >> 1) & 3;
        bool lo = id & 1;
        bgp[i] = (lo ? Bgl : Bgh) + (long)(n0 + r) * K + ch * 8;
        bdst[i] = r * SA + ch * 8;
        blo[i] = lo;
    }

    float acc[4][4][4];
    #pragma unroll
    for (int a = 0; a < 4; a++)
        #pragma unroll
        for (int b = 0; b < 4; b++)
            #pragma unroll
            for (int c = 0; c < 4; c++) acc[a][b][c] = 0.f;

    const int T = K / 32;

    auto load_stage = [&](int stg, int k0) {
        __nv_bfloat16* sb = dsm + stg * STAGE_TOT;
        #pragma unroll
        for (int i = 0; i < 4; i++)
            cp16(sb + (alo[i] ? STAGE_A : 0) + adst[i], agp[i] + k0, aval[i]);
        #pragma unroll
        for (int i = 0; i < 4; i++)
            cp16(sb + 2*STAGE_A + (blo[i] ? STAGE_B : 0) + bdst[i], bgp[i] + k0, true);
        asm volatile("cp.async.commit_group;\n");
    };

    load_stage(0, 0);
    if (T > 1) load_stage(1, 32);

    int st = 0;
    for (int t = 0; t < T; t++) {
        if (t < T - 1) asm volatile("cp.async.wait_group 1;\n" ::: "memory");
        else           asm volatile("cp.async.wait_group 0;\n" ::: "memory");
        __syncthreads();

        unsigned stOff = (unsigned)st * (STAGE_TOT * 2);
        unsigned aBase = smBase + stOff;
        unsigned bBase = smBase + stOff + 4*STAGE_A;
        #pragma unroll
        for (int ks = 0; ks < 2; ks++) {
            unsigned ah[4][4], al[4][4], bh[2][4], bl[2][4];
            #pragma unroll
            for (int mt = 0; mt < 4; mt++) {
                unsigned ad = aoff + mt * (16*SA*2) + ks * 32;
                ldsm4(ah[mt], aBase + ad);
                ldsm4(al[mt], aBase + 2*STAGE_A + ad);
            }
            #pragma unroll
            for (int np = 0; np < 2; np++) {
                unsigned bd = boff + np * (16*SA*2) + ks * 32;
                ldsm4(bh[np], bBase + bd);
                ldsm4(bl[np], bBase + 2*STAGE_B + bd);
            }
            #pragma unroll
            for (int mt = 0; mt < 4; mt++)
                #pragma unroll
                for (int nt = 0; nt < 4; nt++) {
                    unsigned bh2[2] = { bh[nt>>1][(nt&1)*2], bh[nt>>1][(nt&1)*2+1] };
                    unsigned bl2[2] = { bl[nt>>1][(nt&1)*2], bl[nt>>1][(nt&1)*2+1] };
                    mma_bf16(acc[mt][nt], ah[mt], bh2);
                    mma_bf16(acc[mt][nt], ah[mt], bl2);
                    mma_bf16(acc[mt][nt], al[mt], bh2);
                }
        }

        if (t + 2 < T) {
            int ps = st + 2; if (ps >= NSTG) ps -= NSTG;
            load_stage(ps, (t + 2) * 32);
        }
        st = (st + 1 == NSTG) ? 0 : st + 1;
    }

    int g = lane >> 2, q = lane & 3;
    #pragma unroll
    for (int mt = 0; mt < 4; mt++) {
        int r0 = m0 + mbase + mt*16 + g;
        int r1 = r0 + 8;
        bool ok0 = r0 < Meff, ok1 = r1 < Meff;
        #pragma unroll
        for (int nt = 0; nt < 4; nt++) {
            int col = n0 + nbase + nt*8 + 2*q;
            if (ok0) *reinterpret_cast<float2*>(&C[(long)r0 * N + col]) =
                make_float2(acc[mt][nt][0], acc[mt][nt][1]);
            if (ok1) *reinterpret_cast<float2*>(&C[(long)r1 * N + col]) =
                make_float2(acc[mt][nt][2], acc[mt][nt][3]);
        }
    }
}

// ---------------- fused a/b -> beta/decay (warp per token) ----------------
__global__ void ab_kernel(const float* __restrict__ h,
                          const float* __restrict__ Wa, const float* __restrict__ Wb,
                          const float* __restrict__ dtb, const float* __restrict__ alog,
                          float* __restrict__ beta, float* __restrict__ decay) {
    int tok = blockIdx.x * 8 + (threadIdx.x >> 5);
    int lane = threadIdx.x & 31;
    bool isB = lane >= 16;
    int c = lane & 15;
    const float* W = isB ? Wb : Wa;
    const float* hr = h + (long)tok * DMODEL;
    float acc0 = 0.f, acc1 = 0.f, acc2 = 0.f, acc3 = 0.f;
    for (int d0 = 0; d0 < DMODEL; d0 += 32) {
        float hv = hr[d0 + lane];
        #pragma unroll
        for (int j = 0; j < 32; j += 4) {
            float h0 = __shfl_sync(0xffffffffu, hv, j);
            float h1 = __shfl_sync(0xffffffffu, hv, j+1);
            float h2 = __shfl_sync(0xffffffffu, hv, j+2);
            float h3 = __shfl_sync(0xffffffffu, hv, j+3);
            acc0 += h0 * W[(long)(d0 + j    ) * HV + c];
            acc1 += h1 * W[(long)(d0 + j + 1) * HV + c];
            acc2 += h2 * W[(long)(d0 + j + 2) * HV + c];
            acc3 += h3 * W[(long)(d0 + j + 3) * HV + c];
        }
    }
    float s = (acc0 + acc1) + (acc2 + acc3);
    int idx = tok * HV + c;
    if (isB) beta[idx] = sigmoidf(s);
    else {
        float xv = s + dtb[c];
        float sp = (xv > 20.f) ? xv : log1pf(expf(xv));
        decay[idx] = expf(-expf(alog[c]) * sp);
    }
}

// ---------------- conv + silu (+ conv_state tail blocks) ----------------
#define CONV_MAIN_BLOCKS ((SEQ*CONVD + 255)/256)
#define CONV_TAIL_BLOCKS (((KW-1)*CONVD + 255)/256)
__global__ void conv_silu_kernel(const float* __restrict__ qkvz,
                                 const float* __restrict__ conv_state,
                                 const float* __restrict__ w,
                                 float* __restrict__ out,
                                 float* __restrict__ cstate_out) {
    long bid = blockIdx.x;
    if (bid >= CONV_MAIN_BLOCKS) {
        int i = (int)(bid - CONV_MAIN_BLOCKS) * 256 + threadIdx.x;
        if (i < (KW-1) * CONVD) {
            int row = i / CONVD, col = i % CONVD;
            cstate_out[i] = qkvz[(long)(SEQ - (KW-1) + row) * QZD + col];
        }
        return;
    }
    long idx = bid * 256 + threadIdx.x;
    if (idx >= (long)SEQ * CONVD) return;
    int s = (int)(idx / CONVD);
    int c = (int)(idx % CONVD);
    float acc = 0.f;
    #pragma unroll
    for (int j = 0; j < KW; j++) {
        int p = s + j;
        float xv = (p < KW-1) ? conv_state[(long)p * CONVD + c]
                              : qkvz[(long)(p - (KW-1)) * QZD + c];
        acc += xv * w[c * KW + j];
    }
    out[idx] = siluf(acc);
}

// ---------------- l2norm q,k + repeat ----------------
__global__ void l2norm_kernel(const float* __restrict__ qkv,
                              float* __restrict__ qn, float* __restrict__ kn) {
    int gw = blockIdx.x * 8 + (threadIdx.x >> 5);
    int lane = threadIdx.x & 31;
    int s = gw >> 4, rr = gw & 15;
    bool isq = rr < 8;
    int hk = isq ? rr : rr - 8;
    long base = (long)s * CONVD + (isq ? 0 : KEYD) + hk * 64;
    float v0 = qkv[base + lane];
    float v1 = qkv[base + 32 + lane];
    float ss = warp_reduce(v0*v0 + v1*v1);
    float r = rsqrtf(ss + 1e-6f);
    float sc = isq ? 0.125f : 1.f;
    float o0 = v0 * r * sc, o1 = v1 * r * sc;
    float* dst = isq ? qn : kn;
    long b0 = (long)s * VALD + (2*hk) * 64;
    long b1 = (long)s * VALD + (2*hk + 1) * 64;
    dst[b0 + lane] = o0;  dst[b0 + 32 + lane] = o1;
    dst[b1 + lane] = o0;  dst[b1 + 32 + lane] = o1;
}

// ---------------- scan: 8-lane groups, bar per 2 steps ----------------
__global__ void scan_kernel(const float* __restrict__ qn, const float* __restrict__ kn,
                            const float* __restrict__ qkv,
                            const float* __restrict__ decay, const float* __restrict__ beta,
                            const float* __restrict__ state_in,
                            float* __restrict__ o, float* __restrict__ state_out) {
    int h  = blockIdx.x >> 1;
    int cg = blockIdx.x & 1;
    int tid = threadIdx.x;
    int g = tid & 7, vloc = tid >> 3;
    int v = cg * 32 + vloc;
    __shared__ float ks[4][64], qs[4][64], vs[4][32], sc[4][2];
    float S[8];
    #pragma unroll
    for (int i = 0; i < 8; i++)
        S[i] = state_in[(long)h * DK * DV + (long)(g + 8*i) * DV + v];

    float r0 = 0.f, r1 = 0.f;
    auto ldregs = [&](int s0) {
        if (tid < 128) {
            int stp = s0 + (tid >> 6), idx = tid & 63;
            r0 = (stp < SEQ) ? kn[(long)stp * VALD + h*64 + idx] : 0.f;
        } else {
            int t2 = tid - 128;
            int stp = s0 + (t2 >> 6), idx = t2 & 63;
            r0 = (stp < SEQ) ? qn[(long)stp * VALD + h*64 + idx] : 0.f;
        }
        if (tid < 64) {
            int stp = s0 + (tid >> 5), idx = tid & 31;
            r1 = (stp < SEQ) ? qkv[(long)stp * CONVD + 2*KEYD + h*64 + cg*32 + idx] : 0.f;
        } else if (tid < 68) {
            int t2 = tid - 64;
            int stp = s0 + (t2 >> 1);
            if (stp < SEQ)
                r1 = (t2 & 1) ? beta[stp * HV + h] : decay[stp * HV + h];
        }
    };
    auto stregs = [&](int s0) {
        if (tid < 128) {
            int stp = s0 + (tid >> 6);
            if (stp < SEQ) ks[stp & 3][tid & 63] = r0;
        } else {
            int t2 = tid - 128;
            int stp = s0 + (t2 >> 6);
            if (stp < SEQ) qs[stp & 3][t2 & 63] = r0;
        }
        if (tid < 64) {
            int stp = s0 + (tid >> 5);
            if (stp < SEQ) vs[stp & 3][tid & 31] = r1;
        } else if (tid < 68) {
            int t2 = tid - 64;
            int stp = s0 + (t2 >> 1);
            if (stp < SEQ) sc[stp & 3][t2 & 1] = r1;
        }
    };

    ldregs(0); stregs(0);
    ldregs(2);
    __syncthreads();

    for (int s = 0; s < SEQ; s += 2) {
        #pragma unroll
        for (int sub = 0; sub < 2; sub++) {
            int ss = s + sub;
            int b = ss & 3;
            float dec = sc[b][0], bet = sc[b][1], vv = vs[b][vloc];
            float kr[8], qr[8];
            #pragma unroll
            for (int i = 0; i < 8; i++) { kr[i] = ks[b][g + 8*i]; qr[i] = qs[b][g + 8*i]; }
            float p0 = 0.f, p1 = 0.f;
            #pragma unroll
            for (int i = 0; i < 4; i++) { S[i]   *= dec; p0 += kr[i]   * S[i]; }
            #pragma unroll
            for (int i = 4; i < 8; i++) { S[i]   *= dec; p1 += kr[i]   * S[i]; }
            float pm = p0 + p1;
            #pragma unroll
            for (int off = 4; off > 0; off >>= 1) pm += __shfl_xor_sync(0xffffffffu, pm, off);
            float delta = (vv - pm) * bet;
            float o0 = 0.f, o1 = 0.f;
            #pragma unroll
            for (int i = 0; i < 4; i++) { S[i] += kr[i] * delta; o0 += qr[i] * S[i]; }
            #pragma unroll
            for (int i = 4; i < 8; i++) { S[i] += kr[i] * delta; o1 += qr[i] * S[i]; }
            float po = o0 + o1;
            #pragma unroll
            for (int off = 4; off > 0; off >>= 1) po += __shfl_xor_sync(0xffffffffu, po, off);
            if (g == 0) o[(long)ss * VALD + h*64 + v] = po;
        }
        if (s + 2 < SEQ) {
            stregs(s + 2);
            ldregs(s + 4);
        }
        __syncthreads();
    }

    #pragma unroll
    for (int i = 0; i < 8; i++)
        state_out[(long)h * DK * DV + (long)(g + 8*i) * DV + v] = S[i];
}

// ---------------- gated rms-norm -> bf16 ----------------
__global__ void gated_norm_kernel(const float* __restrict__ o, const float* __restrict__ zbase,
                                  const float* __restrict__ nw,
                                  __nv_bfloat16* __restrict__ oh, __nv_bfloat16* __restrict__ ol) {
    int gw = blockIdx.x * 8 + (threadIdx.x >> 5);
    int lane = threadIdx.x & 31;
    int s = gw >> 4, h = gw & 15;
    long base = (long)s * VALD + h * 64;
    long zb   = (long)s * QZD + h * 64;
    float o0 = o[base + lane], o1 = o[base + 32 + lane];
    float ss = warp_reduce(o0*o0 + o1*o1);
    float r = rsqrtf(ss / 64.f + 1e-6f);
    float w0 = 1.f + nw[h*64 + lane], w1 = 1.f + nw[h*64 + 32 + lane];
    float z0 = zbase[zb + lane], z1 = zbase[zb + 32 + lane];
    float r0 = o0 * r * w0 * siluf(z0);
    float r1 = o1 * r * w1 * siluf(z1);
    __nv_bfloat16 hh, hl;
    split_bf16(r0, hh, hl); oh[base + lane] = hh; ol[base + lane] = hl;
    split_bf16(r1, hh, hl); oh[base + 32 + lane] = hh; ol[base + 32 + lane] = hl;
}

// ---------------- router (9 warps: 8 experts + shared gate; zeroes cnt) ----
__global__ void router_kernel(const float* __restrict__ t, const float* __restrict__ rw,
                              const float* __restrict__ wg,
                              int* __restrict__ topi, float* __restrict__ topw,
                              float* __restrict__ gate, int* __restrict__ cnt) {
    int tok = blockIdx.x;
    int wrp = threadIdx.x >> 5, lane = threadIdx.x & 31;
    if (blockIdx.x == 0 && threadIdx.x < NE) cnt[threadIdx.x] = 0;
    __shared__ float lg[NE];
    const float* row = t + (long)tok * DMODEL;
    if (wrp < NE) {
        const float* wr = rw + (long)wrp * DMODEL;
        float s = 0.f;
        for (int d = lane; d < DMODEL; d += 32) s += row[d] * wr[d];
        s = warp_reduce(s);
        if (lane == 0) lg[wrp] = s;
    } else {
        float s = 0.f;
        for (int d = lane; d < DMODEL; d += 32) s += row[d] * wg[d];
        s = warp_reduce(s);
        if (lane == 0) gate[tok] = sigmoidf(s);
    }
    __syncthreads();
    if (threadIdx.x == 0) {
        float mx = -1e30f;
        #pragma unroll
        for (int e = 0; e < NE; e++) mx = fmaxf(mx, lg[e]);
        float ex[NE];
        #pragma unroll
        for (int e = 0; e < NE; e++) ex[e] = expf(lg[e] - mx);
        int b0 = 0; float p0 = -1.f;
        #pragma unroll
        for (int e = 0; e < NE; e++) if (ex[e] > p0) { p0 = ex[e]; b0 = e; }
        int b1 = -1; float p1 = -1.f;
        #pragma unroll
        for (int e = 0; e < NE; e++) if (e != b0 && ex[e] > p1) { p1 = ex[e]; b1 = e; }
        float tot = p0 + p1;
        topi[tok*2] = b0;  topi[tok*2 + 1] = b1;
        topw[tok*2] = p0 / tot;  topw[tok*2 + 1] = p1 / tot;
    }
}

__global__ void build_kernel(const int* __restrict__ topi,
                             int* __restrict__ cnt, int* __restrict__ list,
                             int* __restrict__ pos) {
    int tok = blockIdx.x * blockDim.x + threadIdx.x;
    if (tok >= SEQ) return;
    #pragma unroll
    for (int j = 0; j < TOPK; j++) {
        int e = topi[tok*2 + j];
        int p = atomicAdd(&cnt[e], 1);
        list[e * SEQ + p] = tok;
        pos[tok*2 + j] = p;
    }
}

__global__ void moe_act_kernel(const float* __restrict__ gu, const int* __restrict__ cnt,
                               __nv_bfloat16* __restrict__ acth, __nv_bfloat16* __restrict__ actl) {
    int e = blockIdx.z;
    int idx = blockIdx.x * blockDim.x + threadIdx.x;
    int row = idx >> 9, i = idx & 511;
    if (row >= cnt[e]) return;
    long b = (long)e * SEQ * 1024 + (long)row * 1024;
    float gt = gu[b + i], up = gu[b + 512 + i];
    float v = siluf(gt) * up;
    long o = (long)e * SEQ * IMOE + (long)row * IMOE + i;
    __nv_bfloat16 h, l; split_bf16(v, h, l);
    acth[o] = h; actl[o] = l;
}

__global__ void act2_kernel(const float* __restrict__ sgu,
                            __nv_bfloat16* __restrict__ oh, __nv_bfloat16* __restrict__ ol) {
    long i = (long)blockIdx.x * blockDim.x + threadIdx.x;
    if (i >= (long)SEQ * VALD) return;
    int row = (int)(i >> 10), n = (int)(i & 1023);
    float gv = sgu[(long)row * 2048 + n];
    float uv = sgu[(long)row * 2048 + 1024 + n];
    float v = siluf(gv) * uv;
    __nv_bfloat16 h, l; split_bf16(v, h, l);
    oh[i] = h; ol[i] = l;
}

__global__ void final_kernel(const float* __restrict__ x2, const float* __restrict__ eo,
                             const float* __restrict__ sh, const float* __restrict__ gate,
                             const int* __restrict__ topi, const int* __restrict__ pos,
                             const float* __restrict__ topw,
                             float* __restrict__ out) {
    long i = (long)blockIdx.x * blockDim.x + threadIdx.x;
    if (i >= (long)SEQ * DMODEL) return;
    int row = (int)(i >> 10), col = (int)(i & 1023);
    int e0 = topi[row*2], e1 = topi[row*2+1];
    long r0 = (long)e0 * SEQ + pos[row*2];
    long r1 = (long)e1 * SEQ + pos[row*2+1];
    float w0 = topw[row*2], w1 = topw[row*2+1];
    out[i] = x2[i] + w0 * eo[r0 * DMODEL + col] + w1 * eo[r1 * DMODEL + col]
           + sh[i] * gate[row];
}

// ---------------- host launch ----------------
extern "C" void kernel_launch(void* const* d_in, const int* in_sizes, int n_in,
                              void* d_out, int out_size) {
    const float* x        = (const float*)d_in[0];
    const float* state    = (const float*)d_in[1];
    const float* cstate   = (const float*)d_in[2];
    const float* Wqkv     = (const float*)d_in[3];
    const float* Wz       = (const float*)d_in[4];
    const float* Wa       = (const float*)d_in[5];
    const float* Wb       = (const float*)d_in[6];
    const float* convW    = (const float*)d_in[7];
    const float* dt_bias  = (const float*)d_in[8];
    const float* A_log    = (const float*)d_in[9];
    const float* norm_w   = (const float*)d_in[10];
    const float* Wout     = (const float*)d_in[11];
    const float* routerW  = (const float*)d_in[12];
    const float* Wegu     = (const float*)d_in[13];
    const float* Wed      = (const float*)d_in[14];
    const float* Wsg      = (const float*)d_in[15];
    const float* Wsu      = (const float*)d_in[16];
    const float* Wsd      = (const float*)d_in[17];
    const float* Wseg     = (const float*)d_in[18];
    const float* attn_nw  = (const float*)d_in[19];
    const float* ffn_nw   = (const float*)d_in[20];
    float* out = (float*)d_out;

    float *ph, *pqkvz, *pqkv, *pqn, *pkn, *pbeta, *pdecay, *po, *pattn, *px2, *pt;
    float *ptopw, *pgu, *peo, *psgu, *psh, *pgate;
    int *ptopi, *pcnt, *plist, *ppos;
    __nv_bfloat16 *phh, *phl, *poh, *pol, *pth, *ptl, *pacth, *pactl, *psgh, *psgl;
    __nv_bfloat16 *wqzh, *wqzl, *wouth, *woutl, *wguh, *wgul, *wsdh, *wsdl, *eguh, *egul, *edh, *edl;

    cudaGetSymbolAddress((void**)&ph,     g_h);
    cudaGetSymbolAddress((void**)&phh,    g_hh);
    cudaGetSymbolAddress((void**)&phl,    g_hl);
    cudaGetSymbolAddress((void**)&pqkvz,  g_qkvz);
    cudaGetSymbolAddress((void**)&pqkv,   g_qkv);
    cudaGetSymbolAddress((void**)&pqn,    g_qn);
    cudaGetSymbolAddress((void**)&pkn,    g_kn);
    cudaGetSymbolAddress((void**)&pbeta,  g_beta);
    cudaGetSymbolAddress((void**)&pdecay, g_decay);
    cudaGetSymbolAddress((void**)&po,     g_o);
    cudaGetSymbolAddress((void**)&poh,    g_oh);
    cudaGetSymbolAddress((void**)&pol,    g_ol);
    cudaGetSymbolAddress((void**)&pattn,  g_attn);
    cudaGetSymbolAddress((void**)&px2,    g_x2);
    cudaGetSymbolAddress((void**)&pt,     g_t);
    cudaGetSymbolAddress((void**)&pth,    g_th);
    cudaGetSymbolAddress((void**)&ptl,    g_tl);
    cudaGetSymbolAddress((void**)&ptopi,  g_topi);
    cudaGetSymbolAddress((void**)&ptopw,  g_topw);
    cudaGetSymbolAddress((void**)&ppos,   g_pos);
    cudaGetSymbolAddress((void**)&pcnt,   g_cnt);
    cudaGetSymbolAddress((void**)&plist,  g_list);
    cudaGetSymbolAddress((void**)&pgu,    g_gu);
    cudaGetSymbolAddress((void**)&pacth,  g_acth);
    cudaGetSymbolAddress((void**)&pactl,  g_actl);
    cudaGetSymbolAddress((void**)&peo,    g_eo);
    cudaGetSymbolAddress((void**)&psgu,   g_sgu);
    cudaGetSymbolAddress((void**)&psgh,   g_sgh);
    cudaGetSymbolAddress((void**)&psgl,   g_sgl);
    cudaGetSymbolAddress((void**)&psh,    g_sh);
    cudaGetSymbolAddress((void**)&pgate,  g_gate);
    cudaGetSymbolAddress((void**)&wqzh,   g_wqzT_h);
    cudaGetSymbolAddress((void**)&wqzl,   g_wqzT_l);
    cudaGetSymbolAddress((void**)&wouth,  g_woutT_h);
    cudaGetSymbolAddress((void**)&woutl,  g_woutT_l);
    cudaGetSymbolAddress((void**)&wguh,   g_wguT_h);
    cudaGetSymbolAddress((void**)&wgul,   g_wguT_l);
    cudaGetSymbolAddress((void**)&wsdh,   g_wsdT_h);
    cudaGetSymbolAddress((void**)&wsdl,   g_wsdT_l);
    cudaGetSymbolAddress((void**)&eguh,   g_egu_h);
    cudaGetSymbolAddress((void**)&egul,   g_egu_l);
    cudaGetSymbolAddress((void**)&edh,    g_ed_h);
    cudaGetSymbolAddress((void**)&edl,    g_ed_l);

    cudaFuncSetAttribute(gemm_bf16_kernel<false>,
                         cudaFuncAttributeMaxDynamicSharedMemorySize, GEMM_SMEM);
    cudaFuncSetAttribute(gemm_bf16_kernel<true>,
                         cudaFuncAttributeMaxDynamicSharedMemorySize, GEMM_SMEM);

    dim3 blk(256);

    // ---- launches 1-5: exactly the deps of the qkvz GEMM plus fillers, so
    //      ncu (-s 5 -c 1) profiles launch #6 = the big GEMM ----
    tsplit_kernel<<<dim3(CONVD/32, DMODEL/32), 256>>>(Wqkv, wqzh, wqzl, DMODEL, CONVD);   // 1
    tsplit_kernel<<<dim3(VALD/32, DMODEL/32), 256>>>(Wz, wqzh + (long)CONVD*DMODEL,
                                                     wqzl + (long)CONVD*DMODEL, DMODEL, VALD); // 2
    rmsnorm_kernel<<<SEQ, 256>>>(x, attn_nw, ph, phh, phl);                               // 3
    tsplit_kernel<<<dim3(DMODEL/32, VALD/32), 256>>>(Wout, wouth, woutl, VALD, DMODEL);   // 4
    tsplit_kernel<<<dim3(VALD/32, DMODEL/32), 256>>>(Wsg, wguh, wgul, DMODEL, VALD);      // 5

    // 6: fused qkv|z projection (PROFILED)
    gemm_bf16_kernel<false><<<dim3(QZD/128, SEQ/128, 1), blk, GEMM_SMEM>>>(
        phh, phl, wqzh, wqzl, pqkvz, SEQ, QZD, DMODEL, 0,0,0, nullptr,nullptr,0);

    // rest of weight prep + a/b
    ab_kernel<<<SEQ/8, 256>>>(ph, Wa, Wb, dt_bias, A_log, pbeta, pdecay);
    tsplit_kernel<<<dim3(VALD/32, DMODEL/32), 256>>>(Wsu, wguh + (long)VALD*DMODEL,
                                                     wgul + (long)VALD*DMODEL, DMODEL, VALD);
    tsplit_kernel<<<dim3(DMODEL/32, VALD/32), 256>>>(Wsd, wsdh, wsdl, VALD, DMODEL);
    split_kernel<<<(int)(((long)NE*1024*DMODEL/4 + 255)/256), 256>>>(Wegu, eguh, egul, (long)NE*1024*DMODEL/4);
    split_kernel<<<(int)(((long)NE*DMODEL*IMOE/4 + 255)/256), 256>>>(Wed, edh, edl, (long)NE*DMODEL*IMOE/4);

    // conv (+state tail) and l2norm
    conv_silu_kernel<<<CONV_MAIN_BLOCKS + CONV_TAIL_BLOCKS, 256>>>(
        pqkvz, cstate, convW, pqkv, out + OUT_CONV_OFF);
    l2norm_kernel<<<SEQ*16/8, 256>>>(pqkv, pqn, pkn);

    // scan
    scan_kernel<<<32, 256>>>(pqn, pkn, pqkv, pdecay, pbeta, state, po, out + OUT_STATE_OFF);

    // gated norm -> bf16
    gated_norm_kernel<<<SEQ*16/8, 256>>>(po, pqkvz + CONVD, norm_w, poh, pol);

    // out projection; x2 + rmsnorm
    gemm_bf16_kernel<false><<<dim3(DMODEL/128, SEQ/128, 1), blk, GEMM_SMEM>>>(
        poh, pol, wouth, woutl, pattn, SEQ, DMODEL, VALD, 0,0,0, nullptr,nullptr,0);
    rmsnorm_add_kernel<<<SEQ, 256>>>(x, pattn, ffn_nw, px2, pt, pth, ptl);

    // router (8 expert warps + gate warp, zeroes cnt) + lists
    router_kernel<<<SEQ, 288>>>(pt, routerW, Wseg, ptopi, ptopw, pgate, pcnt);
    build_kernel<<<(SEQ + 255)/256, 256>>>(ptopi, pcnt, plist, ppos);

    // routed experts
    gemm_bf16_kernel<true><<<dim3(1024/128, SEQ/128, NE), blk, GEMM_SMEM>>>(
        pth, ptl, eguh, egul, pgu, SEQ, 2*IMOE, DMODEL,
        0, (long)2*IMOE*DMODEL, (long)SEQ*1024, plist, pcnt, SEQ);
    moe_act_kernel<<<dim3(SEQ*IMOE/256, 1, NE), 256>>>(pgu, pcnt, pacth, pactl);
    gemm_bf16_kernel<true><<<dim3(DMODEL/128, SEQ/128, NE), blk, GEMM_SMEM>>>(
        pacth, pactl, edh, edl, peo, SEQ, DMODEL, IMOE,
        (long)SEQ*IMOE, (long)DMODEL*IMOE, (long)SEQ*DMODEL, nullptr, pcnt, SEQ);

    // shared expert
    gemm_bf16_kernel<false><<<dim3(2048/128, SEQ/128, 1), blk, GEMM_SMEM>>>(
        pth, ptl, wguh, wgul, psgu, SEQ, 2048, DMODEL, 0,0,0, nullptr,nullptr,0);
    act2_kernel<<<(SEQ*VALD + 255)/256, 256>>>(psgu, psgh, psgl);
    gemm_bf16_kernel<false><<<dim3(DMODEL/128, SEQ/128, 1), blk, GEMM_SMEM>>>(
        psgh, psgl, wsdh, wsdl, psh, SEQ, DMODEL, VALD, 0,0,0, nullptr,nullptr,0);

    // final combine
    final_kernel<<<(SEQ*DMODEL + 255)/256, 256>>>(px2, peo, psh, pgate,
                                                  ptopi, ppos, ptopw, out + OUT_X_OFF);
}

// round 17
// speedup vs baseline: 1.1214x; 1.1214x over previous
#include <cuda_runtime.h>
#include <cuda_bf16.h>
#include <math.h>

// ---------------- problem constants ----------------
#define SEQ     2048
#define DMODEL  1024
#define HKN     8
#define DK      64
#define HV      16
#define DV      64
#define KEYD    512
#define VALD    1024
#define CONVD   2048
#define QZD     3072
#define KW      4
#define NE      8
#define TOPK    2
#define IMOE    512

#define OUT_X_OFF     0
#define OUT_STATE_OFF (SEQ*DMODEL)
#define OUT_CONV_OFF  (OUT_STATE_OFF + HV*DK*DV)

// ---------------- scratch ----------------
__device__ float g_h    [SEQ*DMODEL];
__device__ __nv_bfloat16 g_hh[SEQ*DMODEL], g_hl[SEQ*DMODEL];
__device__ float g_qkvz [SEQ*QZD];
__device__ float g_qkv  [SEQ*CONVD];
__device__ float g_qn   [SEQ*VALD];
__device__ float g_kn   [SEQ*VALD];
__device__ float g_beta [SEQ*HV];
__device__ float g_decay[SEQ*HV];
__device__ float g_o    [SEQ*VALD];
__device__ __nv_bfloat16 g_oh[SEQ*VALD], g_ol[SEQ*VALD];
__device__ float g_attn [SEQ*DMODEL];
__device__ float g_x2   [SEQ*DMODEL];
__device__ float g_t    [SEQ*DMODEL];
__device__ __nv_bfloat16 g_th[SEQ*DMODEL], g_tl[SEQ*DMODEL];
__device__ int   g_topi [SEQ*TOPK];
__device__ float g_topw [SEQ*TOPK];
__device__ int   g_pos  [SEQ*TOPK];
__device__ int   g_cnt  [NE];
__device__ int   g_list [NE*SEQ];
__device__ float g_gu   [(long)NE*SEQ*1024];
__device__ __nv_bfloat16 g_acth[(long)NE*SEQ*IMOE], g_actl[(long)NE*SEQ*IMOE];
__device__ float g_eo   [(long)NE*SEQ*DMODEL];
__device__ float g_sgu  [SEQ*2048];
__device__ __nv_bfloat16 g_sgh[SEQ*VALD], g_sgl[SEQ*VALD];
__device__ float g_sh   [SEQ*DMODEL];
__device__ float g_gate [SEQ];
__device__ __nv_bfloat16 g_wqzT_h [QZD*DMODEL],  g_wqzT_l [QZD*DMODEL];
__device__ __nv_bfloat16 g_woutT_h[DMODEL*VALD], g_woutT_l[DMODEL*VALD];
__device__ __nv_bfloat16 g_wguT_h [2048*DMODEL], g_wguT_l [2048*DMODEL];
__device__ __nv_bfloat16 g_wsdT_h [DMODEL*VALD], g_wsdT_l [DMODEL*VALD];
__device__ __nv_bfloat16 g_egu_h  [(long)NE*1024*DMODEL], g_egu_l[(long)NE*1024*DMODEL];
__device__ __nv_bfloat16 g_ed_h   [(long)NE*DMODEL*IMOE], g_ed_l [(long)NE*DMODEL*IMOE];

// ---------------- helpers ----------------
__device__ __forceinline__ float warp_reduce(float v) {
    #pragma unroll
    for (int o = 16; o > 0; o >>= 1) v += __shfl_xor_sync(0xffffffffu, v, o);
    return v;
}
__device__ __forceinline__ float siluf(float x) { return x / (1.f + expf(-x)); }
__device__ __forceinline__ float sigmoidf(float x) { return 1.f / (1.f + expf(-x)); }

__device__ __forceinline__ void mma_bf16(float* c, const unsigned* a, const unsigned* b) {
    asm volatile(
        "mma.sync.aligned.m16n8k16.row.col.f32.bf16.bf16.f32 "
        "{%0,%1,%2,%3}, {%4,%5,%6,%7}, {%8,%9}, {%0,%1,%2,%3};\n"
        : "+f"(c[0]), "+f"(c[1]), "+f"(c[2]), "+f"(c[3])
        : "r"(a[0]), "r"(a[1]), "r"(a[2]), "r"(a[3]), "r"(b[0]), "r"(b[1]));
}
__device__ __forceinline__ void ldsm4(unsigned* r, unsigned addr) {
    asm volatile("ldmatrix.sync.aligned.m8n8.x4.shared.b16 {%0,%1,%2,%3}, [%4];\n"
                 : "=r"(r[0]), "=r"(r[1]), "=r"(r[2]), "=r"(r[3]) : "r"(addr));
}
__device__ __forceinline__ void split_bf16(float v, __nv_bfloat16& hi, __nv_bfloat16& lo) {
    hi = __float2bfloat16(v);
    lo = __float2bfloat16(v - __bfloat162float(hi));
}
__device__ __forceinline__ void cp16(void* sptr, const void* gptr, bool valid) {
    unsigned s = (unsigned)__cvta_generic_to_shared(sptr);
    int sz = valid ? 16 : 0;
    asm volatile("cp.async.cg.shared.global [%0], [%1], 16, %2;\n"
                 :: "r"(s), "l"(gptr), "r"(sz));
}

// ---------------- weight prep ----------------
__global__ void tsplit_kernel(const float* __restrict__ W,
                              __nv_bfloat16* __restrict__ oh, __nv_bfloat16* __restrict__ ol,
                              int K, int N) {
    __shared__ float tile[32][33];
    int n0 = blockIdx.x * 32, k0 = blockIdx.y * 32;
    int tx = threadIdx.x & 31, ty = threadIdx.x >> 5;
    #pragma unroll
    for (int i = 0; i < 32; i += 8)
        tile[ty + i][tx] = W[(long)(k0 + ty + i) * N + n0 + tx];
    __syncthreads();
    #pragma unroll
    for (int i = 0; i < 32; i += 8) {
        float v = tile[tx][ty + i];
        __nv_bfloat16 h, l; split_bf16(v, h, l);
        long o = (long)(n0 + ty + i) * K + k0 + tx;
        oh[o] = h; ol[o] = l;
    }
}

__global__ void split_kernel(const float* __restrict__ in,
                             __nv_bfloat16* __restrict__ oh, __nv_bfloat16* __restrict__ ol,
                             long n4) {
    long i = (long)blockIdx.x * blockDim.x + threadIdx.x;
    if (i >= n4) return;
    float4 v = reinterpret_cast<const float4*>(in)[i];
    __nv_bfloat162 h01, l01, h23, l23;
    __nv_bfloat16 h, l;
    split_bf16(v.x, h, l); h01.x = h; l01.x = l;
    split_bf16(v.y, h, l); h01.y = h; l01.y = l;
    split_bf16(v.z, h, l); h23.x = h; l23.x = l;
    split_bf16(v.w, h, l); h23.y = h; l23.y = l;
    reinterpret_cast<__nv_bfloat162*>(oh)[2*i]   = h01;
    reinterpret_cast<__nv_bfloat162*>(oh)[2*i+1] = h23;
    reinterpret_cast<__nv_bfloat162*>(ol)[2*i]   = l01;
    reinterpret_cast<__nv_bfloat162*>(ol)[2*i+1] = l23;
}

// ---------------- rms norms ----------------
__global__ void rmsnorm_kernel(const float* __restrict__ x, const float* __restrict__ w,
                               float* __restrict__ y,
                               __nv_bfloat16* __restrict__ yh, __nv_bfloat16* __restrict__ yl) {
    int row = blockIdx.x, tid = threadIdx.x;
    const float* xr = x + (long)row * DMODEL;
    float v[4]; float ss = 0.f;
    #pragma unroll
    for (int i = 0; i < 4; i++) { v[i] = xr[tid + 256*i]; ss += v[i]*v[i]; }
    ss = warp_reduce(ss);
    __shared__ float sm[8]; __shared__ float rtot;
    if ((tid & 31) == 0) sm[tid >> 5] = ss;
    __syncthreads();
    if (tid == 0) {
        float t2 = 0.f;
        #pragma unroll
        for (int i = 0; i < 8; i++) t2 += sm[i];
        rtot = rsqrtf(t2 / (float)DMODEL + 1e-6f);
    }
    __syncthreads();
    float r = rtot;
    #pragma unroll
    for (int i = 0; i < 4; i++) {
        long o = (long)row * DMODEL + tid + 256*i;
        float val = v[i] * r * (1.f + w[tid + 256*i]);
        y[o] = val;
        __nv_bfloat16 h, l; split_bf16(val, h, l);
        yh[o] = h; yl[o] = l;
    }
}

__global__ void rmsnorm_add_kernel(const float* __restrict__ x, const float* __restrict__ add,
                                   const float* __restrict__ w,
                                   float* __restrict__ xsum, float* __restrict__ y,
                                   __nv_bfloat16* __restrict__ yh, __nv_bfloat16* __restrict__ yl) {
    int row = blockIdx.x, tid = threadIdx.x;
    const float* xr = x + (long)row * DMODEL;
    const float* ar = add + (long)row * DMODEL;
    float v[4]; float ss = 0.f;
    #pragma unroll
    for (int i = 0; i < 4; i++) { v[i] = xr[tid + 256*i] + ar[tid + 256*i]; ss += v[i]*v[i]; }
    ss = warp_reduce(ss);
    __shared__ float sm[8]; __shared__ float rtot;
    if ((tid & 31) == 0) sm[tid >> 5] = ss;
    __syncthreads();
    if (tid == 0) {
        float t2 = 0.f;
        #pragma unroll
        for (int i = 0; i < 8; i++) t2 += sm[i];
        rtot = rsqrtf(t2 / (float)DMODEL + 1e-6f);
    }
    __syncthreads();
    float r = rtot;
    #pragma unroll
    for (int i = 0; i < 4; i++) {
        long o = (long)row * DMODEL + tid + 256*i;
        xsum[o] = v[i];
        float val = v[i] * r * (1.f + w[tid + 256*i]);
        y[o] = val;
        __nv_bfloat16 h, l; split_bf16(val, h, l);
        yh[o] = h; yl[o] = l;
    }
}

// ---------------- bf16 GEMM 128x128x32, 3-stage cp.async, 1 bar/iter -------
#define SA 40
#define STAGE_A (128*SA)
#define STAGE_B (128*SA)
#define STAGE_TOT (2*STAGE_A + 2*STAGE_B)
#define NSTG 3
#define GEMM_SMEM (NSTG*STAGE_TOT*2)

template<bool AGATHER>
__global__ void __launch_bounds__(256, 1) gemm_bf16_kernel(
        const __nv_bfloat16* __restrict__ Ah_g, const __nv_bfloat16* __restrict__ Al_g,
        const __nv_bfloat16* __restrict__ Bh_g, const __nv_bfloat16* __restrict__ Bl_g,
        float* __restrict__ Cbase,
        int M, int N, int K,
        long aStride, long bStride, long cStride,
        const int* __restrict__ gIdx, const int* __restrict__ gCnt, int gCap) {
    extern __shared__ __nv_bfloat16 dsm[];

    const int e = blockIdx.z;
    const __nv_bfloat16* Agh = Ah_g + (long)e * aStride;
    const __nv_bfloat16* Agl = Al_g + (long)e * aStride;
    const __nv_bfloat16* Bgh = Bh_g + (long)e * bStride;
    const __nv_bfloat16* Bgl = Bl_g + (long)e * bStride;
    float* C = Cbase + (long)e * cStride;

    int Meff = M;
    const int* lst = nullptr;
    if (AGATHER) {
        Meff = gCnt[e];
        lst = gIdx ? (gIdx + e * gCap) : nullptr;
    }
    int m0 = blockIdx.y * 128, n0 = blockIdx.x * 128;
    if (m0 >= Meff) return;

    int tid = threadIdx.x;
    int wid = tid >> 5, lane = tid & 31;
    int mbase = (wid >> 2) * 64;
    int nbase = (wid & 3) * 32;
    int lr = lane & 7, grp = lane >> 3;

    unsigned aoff = ((mbase + (grp & 1)*8 + lr) * SA + (grp >> 1)*8) * 2;
    unsigned boff = ((nbase + (grp >> 1)*8 + lr) * SA + (grp & 1)*8) * 2;
    unsigned smBase = (unsigned)__cvta_generic_to_shared(dsm);

    const __nv_bfloat16* agp[4]; int adst[4]; bool alo[4], aval[4];
    #pragma unroll
    for (int i = 0; i < 4; i++) {
        int id = tid + 256*i;
        int r = id >> 3, ch = (id >> 1) & 3;
        bool lo = id & 1;
        int m = m0 + r;
        bool vld = m < Meff;
        long grow = 0;
        if (vld) grow = (AGATHER && lst) ? (long)lst[m] : (long)m;
        agp[i] = (lo ? Agl : Agh) + grow * K + ch * 8;
        adst[i] = r * SA + ch * 8;
        alo[i] = lo; aval[i] = vld;
    }
    const __nv_bfloat16* bgp[4]; int bdst[4]; bool blo[4];
    #pragma unroll
    for (int i = 0; i < 4; i++) {
        int id = tid + 256*i;
        int r = id >> 3, ch = (id >> 1) & 3;
        bool lo = id & 1;
        bgp[i] = (lo ? Bgl : Bgh) + (long)(n0 + r) * K + ch * 8;
        bdst[i] = r * SA + ch * 8;
        blo[i] = lo;
    }

    float acc[4][4][4];
    #pragma unroll
    for (int a = 0; a < 4; a++)
        #pragma unroll
        for (int b = 0; b < 4; b++)
            #pragma unroll
            for (int c = 0; c < 4; c++) acc[a][b][c] = 0.f;

    const int T = K / 32;

    auto load_stage = [&](int stg, int k0) {
        __nv_bfloat16* sb = dsm + stg * STAGE_TOT;
        #pragma unroll
        for (int i = 0; i < 4; i++)
            cp16(sb + (alo[i] ? STAGE_A : 0) + adst[i], agp[i] + k0, aval[i]);
        #pragma unroll
        for (int i = 0; i < 4; i++)
            cp16(sb + 2*STAGE_A + (blo[i] ? STAGE_B : 0) + bdst[i], bgp[i] + k0, true);
        asm volatile("cp.async.commit_group;\n");
    };

    load_stage(0, 0);
    if (T > 1) load_stage(1, 32);

    int st = 0;
    for (int t = 0; t < T; t++) {
        if (t < T - 1) asm volatile("cp.async.wait_group 1;\n" ::: "memory");
        else           asm volatile("cp.async.wait_group 0;\n" ::: "memory");
        __syncthreads();

        unsigned stOff = (unsigned)st * (STAGE_TOT * 2);
        unsigned aBase = smBase + stOff;
        unsigned bBase = smBase + stOff + 4*STAGE_A;
        #pragma unroll
        for (int ks = 0; ks < 2; ks++) {
            unsigned ah[4][4], al[4][4], bh[2][4], bl[2][4];
            #pragma unroll
            for (int mt = 0; mt < 4; mt++) {
                unsigned ad = aoff + mt * (16*SA*2) + ks * 32;
                ldsm4(ah[mt], aBase + ad);
                ldsm4(al[mt], aBase + 2*STAGE_A + ad);
            }
            #pragma unroll
            for (int np = 0; np < 2; np++) {
                unsigned bd = boff + np * (16*SA*2) + ks * 32;
                ldsm4(bh[np], bBase + bd);
                ldsm4(bl[np], bBase + 2*STAGE_B + bd);
            }
            #pragma unroll
            for (int mt = 0; mt < 4; mt++)
                #pragma unroll
                for (int nt = 0; nt < 4; nt++) {
                    unsigned bh2[2] = { bh[nt>>1][(nt&1)*2], bh[nt>>1][(nt&1)*2+1] };
                    unsigned bl2[2] = { bl[nt>>1][(nt&1)*2], bl[nt>>1][(nt&1)*2+1] };
                    mma_bf16(acc[mt][nt], ah[mt], bh2);
                    mma_bf16(acc[mt][nt], ah[mt], bl2);
                    mma_bf16(acc[mt][nt], al[mt], bh2);
                }
        }

        if (t + 2 < T) {
            int ps = st + 2; if (ps >= NSTG) ps -= NSTG;
            load_stage(ps, (t + 2) * 32);
        }
        st = (st + 1 == NSTG) ? 0 : st + 1;
    }

    int g = lane >> 2, q = lane & 3;
    #pragma unroll
    for (int mt = 0; mt < 4; mt++) {
        int r0 = m0 + mbase + mt*16 + g;
        int r1 = r0 + 8;
        bool ok0 = r0 < Meff, ok1 = r1 < Meff;
        #pragma unroll
        for (int nt = 0; nt < 4; nt++) {
            int col = n0 + nbase + nt*8 + 2*q;
            if (ok0) *reinterpret_cast<float2*>(&C[(long)r0 * N + col]) =
                make_float2(acc[mt][nt][0], acc[mt][nt][1]);
            if (ok1) *reinterpret_cast<float2*>(&C[(long)r1 * N + col]) =
                make_float2(acc[mt][nt][2], acc[mt][nt][3]);
        }
    }
}

// ---------------- fused a/b -> beta/decay (warp per token) ----------------
__global__ void ab_kernel(const float* __restrict__ h,
                          const float* __restrict__ Wa, const float* __restrict__ Wb,
                          const float* __restrict__ dtb, const float* __restrict__ alog,
                          float* __restrict__ beta, float* __restrict__ decay) {
    int tok = blockIdx.x * 8 + (threadIdx.x >> 5);
    int lane = threadIdx.x & 31;
    bool isB = lane >= 16;
    int c = lane & 15;
    const float* W = isB ? Wb : Wa;
    const float* hr = h + (long)tok * DMODEL;
    float acc0 = 0.f, acc1 = 0.f, acc2 = 0.f, acc3 = 0.f;
    for (int d0 = 0; d0 < DMODEL; d0 += 32) {
        float hv = hr[d0 + lane];
        #pragma unroll
        for (int j = 0; j < 32; j += 4) {
            float h0 = __shfl_sync(0xffffffffu, hv, j);
            float h1 = __shfl_sync(0xffffffffu, hv, j+1);
            float h2 = __shfl_sync(0xffffffffu, hv, j+2);
            float h3 = __shfl_sync(0xffffffffu, hv, j+3);
            acc0 += h0 * W[(long)(d0 + j    ) * HV + c];
            acc1 += h1 * W[(long)(d0 + j + 1) * HV + c];
            acc2 += h2 * W[(long)(d0 + j + 2) * HV + c];
            acc3 += h3 * W[(long)(d0 + j + 3) * HV + c];
        }
    }
    float s = (acc0 + acc1) + (acc2 + acc3);
    int idx = tok * HV + c;
    if (isB) beta[idx] = sigmoidf(s);
    else {
        float xv = s + dtb[c];
        float sp = (xv > 20.f) ? xv : log1pf(expf(xv));
        decay[idx] = expf(-expf(alog[c]) * sp);
    }
}

// ---------------- conv + silu (+ conv_state tail blocks) ----------------
#define CONV_MAIN_BLOCKS ((SEQ*CONVD + 255)/256)
#define CONV_TAIL_BLOCKS (((KW-1)*CONVD + 255)/256)
__global__ void conv_silu_kernel(const float* __restrict__ qkvz,
                                 const float* __restrict__ conv_state,
                                 const float* __restrict__ w,
                                 float* __restrict__ out,
                                 float* __restrict__ cstate_out) {
    long bid = blockIdx.x;
    if (bid >= CONV_MAIN_BLOCKS) {
        int i = (int)(bid - CONV_MAIN_BLOCKS) * 256 + threadIdx.x;
        if (i < (KW-1) * CONVD) {
            int row = i / CONVD, col = i % CONVD;
            cstate_out[i] = qkvz[(long)(SEQ - (KW-1) + row) * QZD + col];
        }
        return;
    }
    long idx = bid * 256 + threadIdx.x;
    if (idx >= (long)SEQ * CONVD) return;
    int s = (int)(idx / CONVD);
    int c = (int)(idx % CONVD);
    float acc = 0.f;
    #pragma unroll
    for (int j = 0; j < KW; j++) {
        int p = s + j;
        float xv = (p < KW-1) ? conv_state[(long)p * CONVD + c]
                              : qkvz[(long)(p - (KW-1)) * QZD + c];
        acc += xv * w[c * KW + j];
    }
    out[idx] = siluf(acc);
}

// ---------------- l2norm q,k + repeat ----------------
__global__ void l2norm_kernel(const float* __restrict__ qkv,
                              float* __restrict__ qn, float* __restrict__ kn) {
    int gw = blockIdx.x * 8 + (threadIdx.x >> 5);
    int lane = threadIdx.x & 31;
    int s = gw >> 4, rr = gw & 15;
    bool isq = rr < 8;
    int hk = isq ? rr : rr - 8;
    long base = (long)s * CONVD + (isq ? 0 : KEYD) + hk * 64;
    float v0 = qkv[base + lane];
    float v1 = qkv[base + 32 + lane];
    float ss = warp_reduce(v0*v0 + v1*v1);
    float r = rsqrtf(ss + 1e-6f);
    float sc = isq ? 0.125f : 1.f;
    float o0 = v0 * r * sc, o1 = v1 * r * sc;
    float* dst = isq ? qn : kn;
    long b0 = (long)s * VALD + (2*hk) * 64;
    long b1 = (long)s * VALD + (2*hk + 1) * 64;
    dst[b0 + lane] = o0;  dst[b0 + 32 + lane] = o1;
    dst[b1 + lane] = o0;  dst[b1 + 32 + lane] = o1;
}

// ---------------- scan: 8-lane groups, bar per 2 steps ----------------
__global__ void scan_kernel(const float* __restrict__ qn, const float* __restrict__ kn,
                            const float* __restrict__ qkv,
                            const float* __restrict__ decay, const float* __restrict__ beta,
                            const float* __restrict__ state_in,
                            float* __restrict__ o, float* __restrict__ state_out) {
    int h  = blockIdx.x >> 1;
    int cg = blockIdx.x & 1;
    int tid = threadIdx.x;
    int g = tid & 7, vloc = tid >> 3;
    int v = cg * 32 + vloc;
    __shared__ float ks[4][64], qs[4][64], vs[4][32], sc[4][2];
    float S[8];
    #pragma unroll
    for (int i = 0; i < 8; i++)
        S[i] = state_in[(long)h * DK * DV + (long)(g + 8*i) * DV + v];

    float r0 = 0.f, r1 = 0.f;
    auto ldregs = [&](int s0) {
        if (tid < 128) {
            int stp = s0 + (tid >> 6), idx = tid & 63;
            r0 = (stp < SEQ) ? kn[(long)stp * VALD + h*64 + idx] : 0.f;
        } else {
            int t2 = tid - 128;
            int stp = s0 + (t2 >> 6), idx = t2 & 63;
            r0 = (stp < SEQ) ? qn[(long)stp * VALD + h*64 + idx] : 0.f;
        }
        if (tid < 64) {
            int stp = s0 + (tid >> 5), idx = tid & 31;
            r1 = (stp < SEQ) ? qkv[(long)stp * CONVD + 2*KEYD + h*64 + cg*32 + idx] : 0.f;
        } else if (tid < 68) {
            int t2 = tid - 64;
            int stp = s0 + (t2 >> 1);
            if (stp < SEQ)
                r1 = (t2 & 1) ? beta[stp * HV + h] : decay[stp * HV + h];
        }
    };
    auto stregs = [&](int s0) {
        if (tid < 128) {
            int stp = s0 + (tid >> 6);
            if (stp < SEQ) ks[stp & 3][tid & 63] = r0;
        } else {
            int t2 = tid - 128;
            int stp = s0 + (t2 >> 6);
            if (stp < SEQ) qs[stp & 3][t2 & 63] = r0;
        }
        if (tid < 64) {
            int stp = s0 + (tid >> 5);
            if (stp < SEQ) vs[stp & 3][tid & 31] = r1;
        } else if (tid < 68) {
            int t2 = tid - 64;
            int stp = s0 + (t2 >> 1);
            if (stp < SEQ) sc[stp & 3][t2 & 1] = r1;
        }
    };

    ldregs(0); stregs(0);
    ldregs(2);
    __syncthreads();

    for (int s = 0; s < SEQ; s += 2) {
        #pragma unroll
        for (int sub = 0; sub < 2; sub++) {
            int ss = s + sub;
            int b = ss & 3;
            float dec = sc[b][0], bet = sc[b][1], vv = vs[b][vloc];
            float kr[8], qr[8];
            #pragma unroll
            for (int i = 0; i < 8; i++) { kr[i] = ks[b][g + 8*i]; qr[i] = qs[b][g + 8*i]; }
            float p0 = 0.f, p1 = 0.f;
            #pragma unroll
            for (int i = 0; i < 4; i++) { S[i]   *= dec; p0 += kr[i]   * S[i]; }
            #pragma unroll
            for (int i = 4; i < 8; i++) { S[i]   *= dec; p1 += kr[i]   * S[i]; }
            float pm = p0 + p1;
            #pragma unroll
            for (int off = 4; off > 0; off >>= 1) pm += __shfl_xor_sync(0xffffffffu, pm, off);
            float delta = (vv - pm) * bet;
            float o0 = 0.f, o1 = 0.f;
            #pragma unroll
            for (int i = 0; i < 4; i++) { S[i] += kr[i] * delta; o0 += qr[i] * S[i]; }
            #pragma unroll
            for (int i = 4; i < 8; i++) { S[i] += kr[i] * delta; o1 += qr[i] * S[i]; }
            float po = o0 + o1;
            #pragma unroll
            for (int off = 4; off > 0; off >>= 1) po += __shfl_xor_sync(0xffffffffu, po, off);
            if (g == 0) o[(long)ss * VALD + h*64 + v] = po;
        }
        if (s + 2 < SEQ) {
            stregs(s + 2);
            ldregs(s + 4);
        }
        __syncthreads();
    }

    #pragma unroll
    for (int i = 0; i < 8; i++)
        state_out[(long)h * DK * DV + (long)(g + 8*i) * DV + v] = S[i];
}

// ---------------- gated rms-norm -> bf16 ----------------
__global__ void gated_norm_kernel(const float* __restrict__ o, const float* __restrict__ zbase,
                                  const float* __restrict__ nw,
                                  __nv_bfloat16* __restrict__ oh, __nv_bfloat16* __restrict__ ol) {
    int gw = blockIdx.x * 8 + (threadIdx.x >> 5);
    int lane = threadIdx.x & 31;
    int s = gw >> 4, h = gw & 15;
    long base = (long)s * VALD + h * 64;
    long zb   = (long)s * QZD + h * 64;
    float o0 = o[base + lane], o1 = o[base + 32 + lane];
    float ss = warp_reduce(o0*o0 + o1*o1);
    float r = rsqrtf(ss / 64.f + 1e-6f);
    float w0 = 1.f + nw[h*64 + lane], w1 = 1.f + nw[h*64 + 32 + lane];
    float z0 = zbase[zb + lane], z1 = zbase[zb + 32 + lane];
    float r0 = o0 * r * w0 * siluf(z0);
    float r1 = o1 * r * w1 * siluf(z1);
    __nv_bfloat16 hh, hl;
    split_bf16(r0, hh, hl); oh[base + lane] = hh; ol[base + lane] = hl;
    split_bf16(r1, hh, hl); oh[base + 32 + lane] = hh; ol[base + 32 + lane] = hl;
}

// ---------------- router (9 warps: 8 experts + shared gate; zeroes cnt) ----
__global__ void router_kernel(const float* __restrict__ t, const float* __restrict__ rw,
                              const float* __restrict__ wg,
                              int* __restrict__ topi, float* __restrict__ topw,
                              float* __restrict__ gate, int* __restrict__ cnt) {
    int tok = blockIdx.x;
    int wrp = threadIdx.x >> 5, lane = threadIdx.x & 31;
    if (blockIdx.x == 0 && threadIdx.x < NE) cnt[threadIdx.x] = 0;
    __shared__ float lg[NE];
    const float* row = t + (long)tok * DMODEL;
    if (wrp < NE) {
        const float* wr = rw + (long)wrp * DMODEL;
        float s = 0.f;
        for (int d = lane; d < DMODEL; d += 32) s += row[d] * wr[d];
        s = warp_reduce(s);
        if (lane == 0) lg[wrp] = s;
    } else {
        float s = 0.f;
        for (int d = lane; d < DMODEL; d += 32) s += row[d] * wg[d];
        s = warp_reduce(s);
        if (lane == 0) gate[tok] = sigmoidf(s);
    }
    __syncthreads();
    if (threadIdx.x == 0) {
        float mx = -1e30f;
        #pragma unroll
        for (int e = 0; e < NE; e++) mx = fmaxf(mx, lg[e]);
        float ex[NE];
        #pragma unroll
        for (int e = 0; e < NE; e++) ex[e] = expf(lg[e] - mx);
        int b0 = 0; float p0 = -1.f;
        #pragma unroll
        for (int e = 0; e < NE; e++) if (ex[e] > p0) { p0 = ex[e]; b0 = e; }
        int b1 = -1; float p1 = -1.f;
        #pragma unroll
        for (int e = 0; e < NE; e++) if (e != b0 && ex[e] > p1) { p1 = ex[e]; b1 = e; }
        float tot = p0 + p1;
        topi[tok*2] = b0;  topi[tok*2 + 1] = b1;
        topw[tok*2] = p0 / tot;  topw[tok*2 + 1] = p1 / tot;
    }
}

__global__ void build_kernel(const int* __restrict__ topi,
                             int* __restrict__ cnt, int* __restrict__ list,
                             int* __restrict__ pos) {
    int tok = blockIdx.x * blockDim.x + threadIdx.x;
    if (tok >= SEQ) return;
    #pragma unroll
    for (int j = 0; j < TOPK; j++) {
        int e = topi[tok*2 + j];
        int p = atomicAdd(&cnt[e], 1);
        list[e * SEQ + p] = tok;
        pos[tok*2 + j] = p;
    }
}

__global__ void moe_act_kernel(const float* __restrict__ gu, const int* __restrict__ cnt,
                               __nv_bfloat16* __restrict__ acth, __nv_bfloat16* __restrict__ actl) {
    int e = blockIdx.z;
    int idx = blockIdx.x * blockDim.x + threadIdx.x;
    int row = idx >> 9, i = idx & 511;
    if (row >= cnt[e]) return;
    long b = (long)e * SEQ * 1024 + (long)row * 1024;
    float gt = gu[b + i], up = gu[b + 512 + i];
    float v = siluf(gt) * up;
    long o = (long)e * SEQ * IMOE + (long)row * IMOE + i;
    __nv_bfloat16 h, l; split_bf16(v, h, l);
    acth[o] = h; actl[o] = l;
}

__global__ void act2_kernel(const float* __restrict__ sgu,
                            __nv_bfloat16* __restrict__ oh, __nv_bfloat16* __restrict__ ol) {
    long i = (long)blockIdx.x * blockDim.x + threadIdx.x;
    if (i >= (long)SEQ * VALD) return;
    int row = (int)(i >> 10), n = (int)(i & 1023);
    float gv = sgu[(long)row * 2048 + n];
    float uv = sgu[(long)row * 2048 + 1024 + n];
    float v = siluf(gv) * uv;
    __nv_bfloat16 h, l; split_bf16(v, h, l);
    oh[i] = h; ol[i] = l;
}

__global__ void final_kernel(const float* __restrict__ x2, const float* __restrict__ eo,
                             const float* __restrict__ sh, const float* __restrict__ gate,
                             const int* __restrict__ topi, const int* __restrict__ pos,
                             const float* __restrict__ topw,
                             float* __restrict__ out) {
    long i = (long)blockIdx.x * blockDim.x + threadIdx.x;
    if (i >= (long)SEQ * DMODEL) return;
    int row = (int)(i >> 10), col = (int)(i & 1023);
    int e0 = topi[row*2], e1 = topi[row*2+1];
    long r0 = (long)e0 * SEQ + pos[row*2];
    long r1 = (long)e1 * SEQ + pos[row*2+1];
    float w0 = topw[row*2], w1 = topw[row*2+1];
    out[i] = x2[i] + w0 * eo[r0 * DMODEL + col] + w1 * eo[r1 * DMODEL + col]
           + sh[i] * gate[row];
}

// ---------------- host launch ----------------
extern "C" void kernel_launch(void* const* d_in, const int* in_sizes, int n_in,
                              void* d_out, int out_size) {
    const float* x        = (const float*)d_in[0];
    const float* state    = (const float*)d_in[1];
    const float* cstate   = (const float*)d_in[2];
    const float* Wqkv     = (const float*)d_in[3];
    const float* Wz       = (const float*)d_in[4];
    const float* Wa       = (const float*)d_in[5];
    const float* Wb       = (const float*)d_in[6];
    const float* convW    = (const float*)d_in[7];
    const float* dt_bias  = (const float*)d_in[8];
    const float* A_log    = (const float*)d_in[9];
    const float* norm_w   = (const float*)d_in[10];
    const float* Wout     = (const float*)d_in[11];
    const float* routerW  = (const float*)d_in[12];
    const float* Wegu     = (const float*)d_in[13];
    const float* Wed      = (const float*)d_in[14];
    const float* Wsg      = (const float*)d_in[15];
    const float* Wsu      = (const float*)d_in[16];
    const float* Wsd      = (const float*)d_in[17];
    const float* Wseg     = (const float*)d_in[18];
    const float* attn_nw  = (const float*)d_in[19];
    const float* ffn_nw   = (const float*)d_in[20];
    float* out = (float*)d_out;

    float *ph, *pqkvz, *pqkv, *pqn, *pkn, *pbeta, *pdecay, *po, *pattn, *px2, *pt;
    float *ptopw, *pgu, *peo, *psgu, *psh, *pgate;
    int *ptopi, *pcnt, *plist, *ppos;
    __nv_bfloat16 *phh, *phl, *poh, *pol, *pth, *ptl, *pacth, *pactl, *psgh, *psgl;
    __nv_bfloat16 *wqzh, *wqzl, *wouth, *woutl, *wguh, *wgul, *wsdh, *wsdl, *eguh, *egul, *edh, *edl;

    cudaGetSymbolAddress((void**)&ph,     g_h);
    cudaGetSymbolAddress((void**)&phh,    g_hh);
    cudaGetSymbolAddress((void**)&phl,    g_hl);
    cudaGetSymbolAddress((void**)&pqkvz,  g_qkvz);
    cudaGetSymbolAddress((void**)&pqkv,   g_qkv);
    cudaGetSymbolAddress((void**)&pqn,    g_qn);
    cudaGetSymbolAddress((void**)&pkn,    g_kn);
    cudaGetSymbolAddress((void**)&pbeta,  g_beta);
    cudaGetSymbolAddress((void**)&pdecay, g_decay);
    cudaGetSymbolAddress((void**)&po,     g_o);
    cudaGetSymbolAddress((void**)&poh,    g_oh);
    cudaGetSymbolAddress((void**)&pol,    g_ol);
    cudaGetSymbolAddress((void**)&pattn,  g_attn);
    cudaGetSymbolAddress((void**)&px2,    g_x2);
    cudaGetSymbolAddress((void**)&pt,     g_t);
    cudaGetSymbolAddress((void**)&pth,    g_th);
    cudaGetSymbolAddress((void**)&ptl,    g_tl);
    cudaGetSymbolAddress((void**)&ptopi,  g_topi);
    cudaGetSymbolAddress((void**)&ptopw,  g_topw);
    cudaGetSymbolAddress((void**)&ppos,   g_pos);
    cudaGetSymbolAddress((void**)&pcnt,   g_cnt);
    cudaGetSymbolAddress((void**)&plist,  g_list);
    cudaGetSymbolAddress((void**)&pgu,    g_gu);
    cudaGetSymbolAddress((void**)&pacth,  g_acth);
    cudaGetSymbolAddress((void**)&pactl,  g_actl);
    cudaGetSymbolAddress((void**)&peo,    g_eo);
    cudaGetSymbolAddress((void**)&psgu,   g_sgu);
    cudaGetSymbolAddress((void**)&psgh,   g_sgh);
    cudaGetSymbolAddress((void**)&psgl,   g_sgl);
    cudaGetSymbolAddress((void**)&psh,    g_sh);
    cudaGetSymbolAddress((void**)&pgate,  g_gate);
    cudaGetSymbolAddress((void**)&wqzh,   g_wqzT_h);
    cudaGetSymbolAddress((void**)&wqzl,   g_wqzT_l);
    cudaGetSymbolAddress((void**)&wouth,  g_woutT_h);
    cudaGetSymbolAddress((void**)&woutl,  g_woutT_l);
    cudaGetSymbolAddress((void**)&wguh,   g_wguT_h);
    cudaGetSymbolAddress((void**)&wgul,   g_wguT_l);
    cudaGetSymbolAddress((void**)&wsdh,   g_wsdT_h);
    cudaGetSymbolAddress((void**)&wsdl,   g_wsdT_l);
    cudaGetSymbolAddress((void**)&eguh,   g_egu_h);
    cudaGetSymbolAddress((void**)&egul,   g_egu_l);
    cudaGetSymbolAddress((void**)&edh,    g_ed_h);
    cudaGetSymbolAddress((void**)&edl,    g_ed_l);

    cudaFuncSetAttribute(gemm_bf16_kernel<false>,
                         cudaFuncAttributeMaxDynamicSharedMemorySize, GEMM_SMEM);
    cudaFuncSetAttribute(gemm_bf16_kernel<true>,
                         cudaFuncAttributeMaxDynamicSharedMemorySize, GEMM_SMEM);

    dim3 blk(256);

    // ---- weight prep (R15 champion order) ----
    tsplit_kernel<<<dim3(CONVD/32, DMODEL/32), 256>>>(Wqkv, wqzh, wqzl, DMODEL, CONVD);
    tsplit_kernel<<<dim3(VALD/32, DMODEL/32), 256>>>(Wz, wqzh + (long)CONVD*DMODEL,
                                                     wqzl + (long)CONVD*DMODEL, DMODEL, VALD);
    tsplit_kernel<<<dim3(DMODEL/32, VALD/32), 256>>>(Wout, wouth, woutl, VALD, DMODEL);
    tsplit_kernel<<<dim3(VALD/32, DMODEL/32), 256>>>(Wsg, wguh, wgul, DMODEL, VALD);
    tsplit_kernel<<<dim3(VALD/32, DMODEL/32), 256>>>(Wsu, wguh + (long)VALD*DMODEL,
                                                     wgul + (long)VALD*DMODEL, DMODEL, VALD);
    tsplit_kernel<<<dim3(DMODEL/32, VALD/32), 256>>>(Wsd, wsdh, wsdl, VALD, DMODEL);
    split_kernel<<<(int)(((long)NE*1024*DMODEL/4 + 255)/256), 256>>>(Wegu, eguh, egul, (long)NE*1024*DMODEL/4);
    split_kernel<<<(int)(((long)NE*DMODEL*IMOE/4 + 255)/256), 256>>>(Wed, edh, edl, (long)NE*DMODEL*IMOE/4);

    // 1. attention rms norm
    rmsnorm_kernel<<<SEQ, 256>>>(x, attn_nw, ph, phh, phl);

    // 2. fused qkv|z projection; fused a/b
    gemm_bf16_kernel<false><<<dim3(QZD/128, SEQ/128, 1), blk, GEMM_SMEM>>>(
        phh, phl, wqzh, wqzl, pqkvz, SEQ, QZD, DMODEL, 0,0,0, nullptr,nullptr,0);
    ab_kernel<<<SEQ/8, 256>>>(ph, Wa, Wb, dt_bias, A_log, pbeta, pdecay);

    // conv (+state tail fused) and l2norm
    conv_silu_kernel<<<CONV_MAIN_BLOCKS + CONV_TAIL_BLOCKS, 256>>>(
        pqkvz, cstate, convW, pqkv, out + OUT_CONV_OFF);
    l2norm_kernel<<<SEQ*16/8, 256>>>(pqkv, pqn, pkn);

    // 3. scan
    scan_kernel<<<32, 256>>>(pqn, pkn, pqkv, pdecay, pbeta, state, po, out + OUT_STATE_OFF);

    // 4. gated norm -> bf16
    gated_norm_kernel<<<SEQ*16/8, 256>>>(po, pqkvz + CONVD, norm_w, poh, pol);

    // 5. out projection; x2 + rmsnorm
    gemm_bf16_kernel<false><<<dim3(DMODEL/128, SEQ/128, 1), blk, GEMM_SMEM>>>(
        poh, pol, wouth, woutl, pattn, SEQ, DMODEL, VALD, 0,0,0, nullptr,nullptr,0);
    rmsnorm_add_kernel<<<SEQ, 256>>>(x, pattn, ffn_nw, px2, pt, pth, ptl);

    // 6. router (8 expert warps + gate warp + cnt zero) + lists
    router_kernel<<<SEQ, 288>>>(pt, routerW, Wseg, ptopi, ptopw, pgate, pcnt);
    build_kernel<<<(SEQ + 255)/256, 256>>>(ptopi, pcnt, plist, ppos);

    // 7. routed experts
    gemm_bf16_kernel<true><<<dim3(1024/128, SEQ/128, NE), blk, GEMM_SMEM>>>(
        pth, ptl, eguh, egul, pgu, SEQ, 2*IMOE, DMODEL,
        0, (long)2*IMOE*DMODEL, (long)SEQ*1024, plist, pcnt, SEQ);
    moe_act_kernel<<<dim3(SEQ*IMOE/256, 1, NE), 256>>>(pgu, pcnt, pacth, pactl);
    gemm_bf16_kernel<true><<<dim3(DMODEL/128, SEQ/128, NE), blk, GEMM_SMEM>>>(
        pacth, pactl, edh, edl, peo, SEQ, DMODEL, IMOE,
        (long)SEQ*IMOE, (long)DMODEL*IMOE, (long)SEQ*DMODEL, nullptr, pcnt, SEQ);

    // 8. shared expert
    gemm_bf16_kernel<false><<<dim3(2048/128, SEQ/128, 1), blk, GEMM_SMEM>>>(
        pth, ptl, wguh, wgul, psgu, SEQ, 2048, DMODEL, 0,0,0, nullptr,nullptr,0);
    act2_kernel<<<(SEQ*VALD + 255)/256, 256>>>(psgu, psgh, psgl);
    gemm_bf16_kernel<false><<<dim3(DMODEL/128, SEQ/128, 1), blk, GEMM_SMEM>>>(
        psgh, psgl, wsdh, wsdl, psh, SEQ, DMODEL, VALD, 0,0,0, nullptr,nullptr,0);

    // 9. final combine
    final_kernel<<<(SEQ*DMODEL + 255)/256, 256>>>(px2, peo, psh, pgate,
                                                  ptopi, ppos, ptopw, out + OUT_X_OFF);
}